// round 1
// baseline (speedup 1.0000x reference)
#include <cuda_runtime.h>
#include <cstdint>

#define BATCH 128
#define TDIM  256
#define IND   1024
#define UD    1024

// Scratch for h[b,t,u] (fp32). __device__ global = allowed scratch (no runtime alloc).
__device__ float g_h[(size_t)BATCH * TDIM * UD];

// ---------------------------------------------------------------------------
// GEMM: h[b,t,u] = sum_i x[b,i,t] * W[i,u]
// A[(b*T+t), i] = x[b,i,t]  (M-dim contiguous in memory for fixed i)
// Tile: 128x128, BK=8, 256 threads, 8x8 accum per thread, double-buffered smem.
// Grid: (N/128=8, M/128=256). A 128-row tile never crosses a batch (128 | 256).
// ---------------------------------------------------------------------------
__global__ __launch_bounds__(256, 2)
void snn_gemm_kernel(const float* __restrict__ x, const float* __restrict__ W)
{
    __shared__ float As[2][8][128];   // [buf][k][m]
    __shared__ float Bs[2][8][128];   // [buf][k][n]

    const int tid   = threadIdx.x;
    const int r0    = blockIdx.y * 128;         // global row (b*T + t)
    const int b     = r0 / TDIM;
    const int t0    = r0 % TDIM;
    const int u0    = blockIdx.x * 128;

    const float* xA = x + (size_t)b * IND * TDIM + t0;  // xA[i*TDIM + m]
    const float* wB = W + u0;                           // wB[i*UD + n]

    // loader mapping: 256 threads * float4 = 1024 floats = one 8x128 k-tile
    const int lk = tid >> 5;          // 0..7
    const int lm = (tid & 31) * 4;    // 0,4,...,124

    // prologue: k-tile 0
    float4 a4 = *reinterpret_cast<const float4*>(xA + (size_t)lk * TDIM + lm);
    float4 b4 = *reinterpret_cast<const float4*>(wB + (size_t)lk * UD   + lm);
    *reinterpret_cast<float4*>(&As[0][lk][lm]) = a4;
    *reinterpret_cast<float4*>(&Bs[0][lk][lm]) = b4;
    __syncthreads();

    float acc[8][8];
    #pragma unroll
    for (int i = 0; i < 8; i++)
        #pragma unroll
        for (int j = 0; j < 8; j++)
            acc[i][j] = 0.0f;

    const int tm = (tid >> 4) * 8;    // 0..120
    const int tn = (tid & 15) * 8;    // 0..120

    const int NKT = IND / 8;          // 128 k-tiles
    for (int kt = 0; kt < NKT; kt++) {
        const int cbuf = kt & 1;
        const int nbuf = cbuf ^ 1;

        // issue next-tile global loads early (latency overlap with compute)
        if (kt + 1 < NKT) {
            const int i0 = (kt + 1) * 8;
            a4 = *reinterpret_cast<const float4*>(xA + (size_t)(i0 + lk) * TDIM + lm);
            b4 = *reinterpret_cast<const float4*>(wB + (size_t)(i0 + lk) * UD   + lm);
        }

        #pragma unroll
        for (int kk = 0; kk < 8; kk++) {
            float ar[8], br[8];
            *reinterpret_cast<float4*>(&ar[0]) = *reinterpret_cast<const float4*>(&As[cbuf][kk][tm]);
            *reinterpret_cast<float4*>(&ar[4]) = *reinterpret_cast<const float4*>(&As[cbuf][kk][tm + 4]);
            *reinterpret_cast<float4*>(&br[0]) = *reinterpret_cast<const float4*>(&Bs[cbuf][kk][tn]);
            *reinterpret_cast<float4*>(&br[4]) = *reinterpret_cast<const float4*>(&Bs[cbuf][kk][tn + 4]);
            #pragma unroll
            for (int i = 0; i < 8; i++)
                #pragma unroll
                for (int j = 0; j < 8; j++)
                    acc[i][j] = fmaf(ar[i], br[j], acc[i][j]);
        }

        if (kt + 1 < NKT) {
            *reinterpret_cast<float4*>(&As[nbuf][lk][lm]) = a4;
            *reinterpret_cast<float4*>(&Bs[nbuf][lk][lm]) = b4;
        }
        __syncthreads();
    }

    // epilogue: h[b, t0+row, u0+col]
    float* hp = g_h + (size_t)(r0 + tm) * UD + u0 + tn;
    #pragma unroll
    for (int i = 0; i < 8; i++) {
        *reinterpret_cast<float4*>(hp + (size_t)i * UD)
            = make_float4(acc[i][0], acc[i][1], acc[i][2], acc[i][3]);
        *reinterpret_cast<float4*>(hp + (size_t)i * UD + 4)
            = make_float4(acc[i][4], acc[i][5], acc[i][6], acc[i][7]);
    }
}

// ---------------------------------------------------------------------------
// Temporal LIF scan. One thread per (b,u); sequential over t.
//   s      = sigmoid(v - 1)
//   v_next = (0.85*v + syn) * (1 - s)
//   syn    = 0.9*syn + h[b,t,u]
//   out[t,b,u] = s
// Reads h coalesced (u contiguous across threads), writes out coalesced.
// ---------------------------------------------------------------------------
__global__ __launch_bounds__(256)
void snn_scan_kernel(float* __restrict__ out)
{
    const int idx = blockIdx.x * blockDim.x + threadIdx.x;   // 0 .. B*U-1
    const int b = idx >> 10;       // / UD
    const int u = idx & (UD - 1);

    const float* hp = g_h + (size_t)b * TDIM * UD + u;
    float* op = out + (size_t)b * UD + u;

    float v = 0.0f, syn = 0.0f;
    #pragma unroll 4
    for (int t = 0; t < TDIM; t++) {
        const float s  = 1.0f / (1.0f + expf(1.0f - v));     // sigmoid(v - 1)
        const float hv = hp[(size_t)t * UD];
        const float vn = (0.85f * v + syn) * (1.0f - s);
        syn = 0.9f * syn + hv;
        v   = vn;
        op[(size_t)t * (BATCH * UD)] = s;
    }
}

// ---------------------------------------------------------------------------
extern "C" void kernel_launch(void* const* d_in, const int* in_sizes, int n_in,
                              void* d_out, int out_size)
{
    const float* x = (const float*)d_in[0];   // [128, 1024, 256]
    const float* W = (const float*)d_in[1];   // [1024, 1024]
    float* out = (float*)d_out;               // [256, 128, 1024]

    dim3 ggrid(UD / 128, (BATCH * TDIM) / 128);   // (8, 256)
    snn_gemm_kernel<<<ggrid, 256>>>(x, W);

    snn_scan_kernel<<<(BATCH * UD) / 256, 256>>>(out);
}

// round 4
// speedup vs baseline: 1.0722x; 1.0722x over previous
#include <cuda_runtime.h>
#include <cstdint>
#include <cstdio>

#define BATCH 128
#define TDIM  256
#define IND   1024
#define UD    1024
#define MTOT  (BATCH * TDIM)        // 32768

#define BK    8
#define LDA   136                   // 128 + 8 pad floats -> conflict-free fragment LDS
#define NIT   (IND / BK)            // 128 mainloop iters

// ---------------------------------------------------------------------------
// Scratch (__device__ global = allowed scratch)
// ---------------------------------------------------------------------------
__device__ float g_h[(size_t)MTOT * UD];     // 128 MB h[m,u]

// ---------------------------------------------------------------------------
// tf32 helpers (base ISA, works on compute_100 / sm_100)
// ---------------------------------------------------------------------------
__device__ __forceinline__ uint32_t f2tf(float f) {
    uint32_t u;
    asm("cvt.rna.tf32.f32 %0, %1;" : "=r"(u) : "f"(f));
    return u;
}

// m16n8k8 tf32 mma, acc in place
__device__ __forceinline__ void mma8(float* c, const uint32_t* a, uint32_t b0, uint32_t b1) {
    asm volatile(
        "mma.sync.aligned.m16n8k8.row.col.f32.tf32.tf32.f32 "
        "{%0,%1,%2,%3}, {%4,%5,%6,%7}, {%8,%9}, {%0,%1,%2,%3};"
        : "+f"(c[0]), "+f"(c[1]), "+f"(c[2]), "+f"(c[3])
        : "r"(a[0]), "r"(a[1]), "r"(a[2]), "r"(a[3]), "r"(b0), "r"(b1));
}

// split fp32 -> (tf32 hi, tf32 lo) and store both to smem
__device__ __forceinline__ void split_store(uint32_t* hi, uint32_t* lo, int idx, float4 v) {
    float vv[4] = {v.x, v.y, v.z, v.w};
    #pragma unroll
    for (int j = 0; j < 4; j++) {
        uint32_t h = f2tf(vv[j]);
        float r = vv[j] - __uint_as_float(h);   // exact (tf32 value is fp32-representable)
        hi[idx + j] = h;
        lo[idx + j] = f2tf(r);
    }
}

// ---------------------------------------------------------------------------
// GEMM: h[m,u] = sum_k A[m,k] * W[k,u],  A[(b*256+t), k] = x[b,k,t]
// 3-pass tf32 split: Ahi*Bhi + Alo*Bhi + Ahi*Blo  (fp32 accum)
// CTA tile 128x128, BK=8, double-buffered static smem, 8 warps (4m x 2n).
// ---------------------------------------------------------------------------
__global__ __launch_bounds__(256)
void gemm_tf32_kernel(const float* __restrict__ x, const float* __restrict__ W)
{
    __shared__ uint32_t smA[2][2][BK * LDA];   // [stage][hi/lo][k][m]
    __shared__ uint32_t smB[2][2][BK * LDA];   // [stage][hi/lo][k][n]

    const int tid  = threadIdx.x;
    const int lane = tid & 31;
    const int wid  = tid >> 5;
    const int warpM = wid & 3;                 // 0..3 -> m offset *32
    const int warpN = wid >> 2;                // 0..1 -> n offset *64
    const int qid  = lane >> 2;                // 0..7
    const int qt   = lane & 3;                 // 0..3

    const int r0 = blockIdx.y * 128;           // m tile base (b*256 + t)
    const int b  = r0 / TDIM;
    const int t0 = r0 % TDIM;
    const int u0 = blockIdx.x * 128;

    // loader: 256 threads cover one 8x128 fp32 tile per operand (float4 each)
    const int lrow = tid >> 5;                 // 0..7 (k within stage)
    const int lcol = (tid & 31) * 4;           // 0..124
    const int sidx = lrow * LDA + lcol;
    const float* xp = x + (size_t)b * IND * TDIM + t0 + lcol;   // + k*TDIM
    const float* wp = W + u0 + lcol;                            // + k*UD

    float acc[2][8][4];
    #pragma unroll
    for (int mt = 0; mt < 2; mt++)
        #pragma unroll
        for (int nt = 0; nt < 8; nt++)
            #pragma unroll
            for (int j = 0; j < 4; j++)
                acc[mt][nt][j] = 0.0f;

    // stage 0
    {
        float4 a4 = *reinterpret_cast<const float4*>(xp + (size_t)lrow * TDIM);
        float4 b4 = *reinterpret_cast<const float4*>(wp + (size_t)lrow * UD);
        split_store(smA[0][0], smA[0][1], sidx, a4);
        split_store(smB[0][0], smB[0][1], sidx, b4);
    }
    __syncthreads();

    const int mbase = warpM * 32 + qid;
    const int nbase = warpN * 64 + qid;

    for (int kt = 0; kt < NIT; kt++) {
        const int cb = kt & 1;
        float4 a4, b4;
        if (kt + 1 < NIT) {
            const int k0 = (kt + 1) * BK;
            a4 = *reinterpret_cast<const float4*>(xp + (size_t)(k0 + lrow) * TDIM);
            b4 = *reinterpret_cast<const float4*>(wp + (size_t)(k0 + lrow) * UD);
        }

        const uint32_t* Ah = smA[cb][0];
        const uint32_t* Al = smA[cb][1];
        const uint32_t* Bh = smB[cb][0];
        const uint32_t* Bl = smB[cb][1];

        // A fragments (hi + lo) for both 16-row m tiles
        uint32_t ahi[2][4], alo[2][4];
        #pragma unroll
        for (int mt = 0; mt < 2; mt++) {
            const int m = mbase + mt * 16;
            ahi[mt][0] = Ah[qt * LDA + m];
            ahi[mt][1] = Ah[qt * LDA + m + 8];
            ahi[mt][2] = Ah[(qt + 4) * LDA + m];
            ahi[mt][3] = Ah[(qt + 4) * LDA + m + 8];
            alo[mt][0] = Al[qt * LDA + m];
            alo[mt][1] = Al[qt * LDA + m + 8];
            alo[mt][2] = Al[(qt + 4) * LDA + m];
            alo[mt][3] = Al[(qt + 4) * LDA + m + 8];
        }

        #pragma unroll
        for (int nt = 0; nt < 8; nt++) {
            const int n = nbase + nt * 8;
            const uint32_t bh0 = Bh[qt * LDA + n];
            const uint32_t bh1 = Bh[(qt + 4) * LDA + n];
            const uint32_t bl0 = Bl[qt * LDA + n];
            const uint32_t bl1 = Bl[(qt + 4) * LDA + n];
            #pragma unroll
            for (int mt = 0; mt < 2; mt++) {
                mma8(acc[mt][nt], ahi[mt], bh0, bh1);   // hi*hi
                mma8(acc[mt][nt], alo[mt], bh0, bh1);   // lo*hi
                mma8(acc[mt][nt], ahi[mt], bl0, bl1);   // hi*lo
            }
        }

        if (kt + 1 < NIT) {
            const int nb = cb ^ 1;
            split_store(smA[nb][0], smA[nb][1], sidx, a4);
            split_store(smB[nb][0], smB[nb][1], sidx, b4);
        }
        __syncthreads();
    }

    // epilogue: c frag layout d0=(m=qid, n=2qt), d1=n+1, d2/d3 = m+8
    #pragma unroll
    for (int mt = 0; mt < 2; mt++) {
        const int row = r0 + warpM * 32 + mt * 16 + qid;
        #pragma unroll
        for (int nt = 0; nt < 8; nt++) {
            const int col = u0 + warpN * 64 + nt * 8 + 2 * qt;
            float* gp = g_h + (size_t)row * UD + col;
            *reinterpret_cast<float2*>(gp) =
                make_float2(acc[mt][nt][0], acc[mt][nt][1]);
            *reinterpret_cast<float2*>(gp + (size_t)8 * UD) =
                make_float2(acc[mt][nt][2], acc[mt][nt][3]);
        }
    }
}

// ---------------------------------------------------------------------------
// Temporal LIF scan: one thread per (b,u), sequential over t=0..255.
//   s = sigmoid(v - 1); v' = (0.85 v + syn)(1 - s); syn' = 0.9 syn + h
// ---------------------------------------------------------------------------
__global__ __launch_bounds__(256)
void snn_scan_kernel(float* __restrict__ out)
{
    const int idx = blockIdx.x * blockDim.x + threadIdx.x;
    const int b = idx >> 10;
    const int u = idx & (UD - 1);

    const float* hp = g_h + (size_t)b * TDIM * UD + u;
    float* op = out + (size_t)b * UD + u;

    float v = 0.0f, syn = 0.0f;
    #pragma unroll 4
    for (int t = 0; t < TDIM; t++) {
        const float s  = 1.0f / (1.0f + expf(1.0f - v));
        const float hv = hp[(size_t)t * UD];
        const float vn = (0.85f * v + syn) * (1.0f - s);
        syn = 0.9f * syn + hv;
        v   = vn;
        op[(size_t)t * (BATCH * UD)] = s;
    }
}

// ---------------------------------------------------------------------------
extern "C" void kernel_launch(void* const* d_in, const int* in_sizes, int n_in,
                              void* d_out, int out_size)
{
    const float* x = (const float*)d_in[0];   // [128, 1024, 256]
    const float* W = (const float*)d_in[1];   // [1024, 1024]
    float* out = (float*)d_out;               // [256, 128, 1024]

    dim3 gg(UD / 128, MTOT / 128);            // (8, 256): x-fastest -> same-A CTAs
    gemm_tf32_kernel<<<gg, 256>>>(x, W);      //   adjacent -> L2 reuse of x rows

    snn_scan_kernel<<<(BATCH * UD) / 256, 256>>>(out);
}

// round 5
// speedup vs baseline: 2.0630x; 1.9240x over previous
#include <cuda_runtime.h>
#include <cuda_bf16.h>
#include <cstdint>

#define BATCH 128
#define TDIM  256
#define IND   1024
#define UD    1024
#define MTOT  (BATCH * TDIM)        // 32768

#define BK    16                    // k per mainloop stage
#define KP    8                     // k-pairs per stage (BK/2)
#define LDW   136                   // 32-bit words per k-pair row (128 + 8 pad)
#define NIT   (IND / BK)            // 64 mainloop iters

// ---------------------------------------------------------------------------
// Scratch (__device__ global = allowed scratch)
// ---------------------------------------------------------------------------
__device__ float g_h[(size_t)MTOT * UD];     // 128 MB  h[m,u]

// ---------------------------------------------------------------------------
// bf16 m16n8k16 mma (base ISA, compiles for compute_100)
// ---------------------------------------------------------------------------
__device__ __forceinline__ void mma16(float* c, const uint32_t* a, uint32_t b0, uint32_t b1) {
    asm volatile(
        "mma.sync.aligned.m16n8k16.row.col.f32.bf16.bf16.f32 "
        "{%0,%1,%2,%3}, {%4,%5,%6,%7}, {%8,%9}, {%0,%1,%2,%3};"
        : "+f"(c[0]), "+f"(c[1]), "+f"(c[2]), "+f"(c[3])
        : "r"(a[0]), "r"(a[1]), "r"(a[2]), "r"(a[3]), "r"(b0), "r"(b1));
}

// Split two fp32 values (same m/n, consecutive k) into packed bf16x2 hi + lo words.
// word low half = k-even element, high half = k-odd element.
__device__ __forceinline__ void pack_split(float a, float b, uint32_t& hw, uint32_t& lw) {
    __nv_bfloat162 h2 = __floats2bfloat162_rn(a, b);      // x=a(low), y=b(high)
    float2 hf = __bfloat1622float2(h2);
    __nv_bfloat162 l2 = __floats2bfloat162_rn(a - hf.x, b - hf.y);
    hw = *reinterpret_cast<uint32_t*>(&h2);
    lw = *reinterpret_cast<uint32_t*>(&l2);
}

__device__ __forceinline__ void sts128(uint32_t* base, int idx, const uint32_t* w) {
    *reinterpret_cast<uint4*>(base + idx) = make_uint4(w[0], w[1], w[2], w[3]);
}

// ---------------------------------------------------------------------------
// GEMM: h[m,u] = sum_k A[m,k] * W[k,u],  A[(b*256+t), k] = x[b,k,t]
// 3-pass bf16 split: Ahi*Bhi + Alo*Bhi + Ahi*Blo  (fp32 accum)
// CTA 128x128, BK=16, double-buffered static smem with packed k-pair words,
// 8 warps (4m x 2n), warp tile 32x64, m16n8k16.
// ---------------------------------------------------------------------------
__global__ __launch_bounds__(256)
void gemm_bf16_kernel(const float* __restrict__ x, const float* __restrict__ W)
{
    // [stage][hi/lo][kpair*LDW + m]: word packs (k=2kp, k=2kp+1) at column m
    __shared__ uint32_t smA[2][2][KP * LDW];
    __shared__ uint32_t smB[2][2][KP * LDW];

    const int tid  = threadIdx.x;
    const int lane = tid & 31;
    const int wid  = tid >> 5;
    const int warpM = wid & 3;                 // m offset *32
    const int warpN = wid >> 2;                // n offset *64
    const int qid  = lane >> 2;                // 0..7
    const int qt   = lane & 3;                 // 0..3

    const int r0 = blockIdx.y * 128;           // m tile base (b*256 + t)
    const int b  = r0 / TDIM;
    const int t0 = r0 % TDIM;
    const int u0 = blockIdx.x * 128;

    // loader: thread covers k-pair row (tid>>5) at 4 consecutive m/n columns
    const int lkp  = tid >> 5;                 // 0..7
    const int lcol = (tid & 31) * 4;           // 0..124
    const int sidx = lkp * LDW + lcol;
    const float* xp = x + (size_t)b * IND * TDIM + t0 + lcol;   // + k*TDIM
    const float* wp = W + u0 + lcol;                            // + k*UD

    float acc[2][8][4];
    #pragma unroll
    for (int mt = 0; mt < 2; mt++)
        #pragma unroll
        for (int nt = 0; nt < 8; nt++)
            #pragma unroll
            for (int j = 0; j < 4; j++)
                acc[mt][nt][j] = 0.0f;

    // ---- stage 0 load ----
    {
        float4 a0 = *reinterpret_cast<const float4*>(xp + (size_t)(2 * lkp)     * TDIM);
        float4 a1 = *reinterpret_cast<const float4*>(xp + (size_t)(2 * lkp + 1) * TDIM);
        float4 b0 = *reinterpret_cast<const float4*>(wp + (size_t)(2 * lkp)     * UD);
        float4 b1 = *reinterpret_cast<const float4*>(wp + (size_t)(2 * lkp + 1) * UD);
        uint32_t hw[4], lw[4];
        pack_split(a0.x, a1.x, hw[0], lw[0]); pack_split(a0.y, a1.y, hw[1], lw[1]);
        pack_split(a0.z, a1.z, hw[2], lw[2]); pack_split(a0.w, a1.w, hw[3], lw[3]);
        sts128(smA[0][0], sidx, hw); sts128(smA[0][1], sidx, lw);
        pack_split(b0.x, b1.x, hw[0], lw[0]); pack_split(b0.y, b1.y, hw[1], lw[1]);
        pack_split(b0.z, b1.z, hw[2], lw[2]); pack_split(b0.w, b1.w, hw[3], lw[3]);
        sts128(smB[0][0], sidx, hw); sts128(smB[0][1], sidx, lw);
    }
    __syncthreads();

    const int mbase = warpM * 32 + qid;
    const int nbase = warpN * 64 + qid;

    for (int kt = 0; kt < NIT; kt++) {
        const int cb = kt & 1;
        float4 pa0, pa1, pb0, pb1;
        if (kt + 1 < NIT) {
            const int k0 = (kt + 1) * BK;
            pa0 = *reinterpret_cast<const float4*>(xp + (size_t)(k0 + 2 * lkp)     * TDIM);
            pa1 = *reinterpret_cast<const float4*>(xp + (size_t)(k0 + 2 * lkp + 1) * TDIM);
            pb0 = *reinterpret_cast<const float4*>(wp + (size_t)(k0 + 2 * lkp)     * UD);
            pb1 = *reinterpret_cast<const float4*>(wp + (size_t)(k0 + 2 * lkp + 1) * UD);
        }

        const uint32_t* Ah = smA[cb][0];
        const uint32_t* Al = smA[cb][1];
        const uint32_t* Bh = smB[cb][0];
        const uint32_t* Bl = smB[cb][1];

        // A fragments: a0=(row qid, kp qt) a1=(row+8) a2=(row, kp qt+4) a3=(row+8)
        uint32_t ahi[2][4], alo[2][4];
        #pragma unroll
        for (int mt = 0; mt < 2; mt++) {
            const int m = mbase + mt * 16;
            ahi[mt][0] = Ah[qt * LDW + m];
            ahi[mt][1] = Ah[qt * LDW + m + 8];
            ahi[mt][2] = Ah[(qt + 4) * LDW + m];
            ahi[mt][3] = Ah[(qt + 4) * LDW + m + 8];
            alo[mt][0] = Al[qt * LDW + m];
            alo[mt][1] = Al[qt * LDW + m + 8];
            alo[mt][2] = Al[(qt + 4) * LDW + m];
            alo[mt][3] = Al[(qt + 4) * LDW + m + 8];
        }

        #pragma unroll
        for (int nt = 0; nt < 8; nt++) {
            const int n = nbase + nt * 8;
            const uint32_t bh0 = Bh[qt * LDW + n];
            const uint32_t bh1 = Bh[(qt + 4) * LDW + n];
            const uint32_t bl0 = Bl[qt * LDW + n];
            const uint32_t bl1 = Bl[(qt + 4) * LDW + n];
            #pragma unroll
            for (int mt = 0; mt < 2; mt++) {
                mma16(acc[mt][nt], ahi[mt], bh0, bh1);   // hi*hi
                mma16(acc[mt][nt], alo[mt], bh0, bh1);   // lo*hi
                mma16(acc[mt][nt], ahi[mt], bl0, bl1);   // hi*lo
            }
        }

        if (kt + 1 < NIT) {
            const int nb = cb ^ 1;
            uint32_t hw[4], lw[4];
            pack_split(pa0.x, pa1.x, hw[0], lw[0]); pack_split(pa0.y, pa1.y, hw[1], lw[1]);
            pack_split(pa0.z, pa1.z, hw[2], lw[2]); pack_split(pa0.w, pa1.w, hw[3], lw[3]);
            sts128(smA[nb][0], sidx, hw); sts128(smA[nb][1], sidx, lw);
            pack_split(pb0.x, pb1.x, hw[0], lw[0]); pack_split(pb0.y, pb1.y, hw[1], lw[1]);
            pack_split(pb0.z, pb1.z, hw[2], lw[2]); pack_split(pb0.w, pb1.w, hw[3], lw[3]);
            sts128(smB[nb][0], sidx, hw); sts128(smB[nb][1], sidx, lw);
        }
        __syncthreads();
    }

    // epilogue: c frag d0=(m=qid, n=2qt), d1=n+1, d2/d3 at m+8
    #pragma unroll
    for (int mt = 0; mt < 2; mt++) {
        const int row = r0 + warpM * 32 + mt * 16 + qid;
        #pragma unroll
        for (int nt = 0; nt < 8; nt++) {
            const int col = u0 + warpN * 64 + nt * 8 + 2 * qt;
            float* gp = g_h + (size_t)row * UD + col;
            *reinterpret_cast<float2*>(gp) =
                make_float2(acc[mt][nt][0], acc[mt][nt][1]);
            *reinterpret_cast<float2*>(gp + (size_t)8 * UD) =
                make_float2(acc[mt][nt][2], acc[mt][nt][3]);
        }
    }
}

// ---------------------------------------------------------------------------
// Temporal LIF scan: 4 independent (b,u) chains per thread (float4), ILP=4.
//   s = sigmoid(v - 1); v' = (0.85 v + syn)(1 - s); syn' = 0.9 syn + h
// ---------------------------------------------------------------------------
__global__ __launch_bounds__(256)
void snn_scan_kernel(float* __restrict__ out)
{
    const int idx = blockIdx.x * blockDim.x + threadIdx.x;   // 0 .. B*U/4-1
    const int b  = idx >> 8;            // / (UD/4)
    const int u  = (idx & 255) * 4;

    const float4* hp = reinterpret_cast<const float4*>(g_h + (size_t)b * TDIM * UD + u);
    float4* op = reinterpret_cast<float4*>(out + (size_t)b * UD + u);

    float4 v   = make_float4(0.f, 0.f, 0.f, 0.f);
    float4 syn = make_float4(0.f, 0.f, 0.f, 0.f);
    #pragma unroll 4
    for (int t = 0; t < TDIM; t++) {
        const float4 h = hp[(size_t)t * (UD / 4)];
        float4 s;
        s.x = 1.0f / (1.0f + __expf(1.0f - v.x));
        s.y = 1.0f / (1.0f + __expf(1.0f - v.y));
        s.z = 1.0f / (1.0f + __expf(1.0f - v.z));
        s.w = 1.0f / (1.0f + __expf(1.0f - v.w));
        float4 vn;
        vn.x = (0.85f * v.x + syn.x) * (1.0f - s.x);
        vn.y = (0.85f * v.y + syn.y) * (1.0f - s.y);
        vn.z = (0.85f * v.z + syn.z) * (1.0f - s.z);
        vn.w = (0.85f * v.w + syn.w) * (1.0f - s.w);
        syn.x = 0.9f * syn.x + h.x;
        syn.y = 0.9f * syn.y + h.y;
        syn.z = 0.9f * syn.z + h.z;
        syn.w = 0.9f * syn.w + h.w;
        v = vn;
        op[(size_t)t * (BATCH * UD / 4)] = s;
    }
}

// ---------------------------------------------------------------------------
extern "C" void kernel_launch(void* const* d_in, const int* in_sizes, int n_in,
                              void* d_out, int out_size)
{
    const float* x = (const float*)d_in[0];   // [128, 1024, 256]
    const float* W = (const float*)d_in[1];   // [1024, 1024]
    float* out = (float*)d_out;               // [256, 128, 1024]

    dim3 gg(UD / 128, MTOT / 128);            // (8, 256)
    gemm_bf16_kernel<<<gg, 256>>>(x, W);

    snn_scan_kernel<<<(BATCH * UD / 4) / 256, 256>>>(out);
}